// round 4
// baseline (speedup 1.0000x reference)
#include <cuda_runtime.h>
#include <cstdint>

#define BATCH 8
#define IN_F 4096
#define OUT_F 12288
#define GS 128
#define NG 32
#define OPW 4          // outputs per warp
#define WPB 2          // warps per block
#define TPB (WPB * 32)

typedef unsigned long long u64;

__device__ float g_sx[BATCH * NG];      // per-batch per-group sums of x

__device__ __forceinline__ u64 pack2(float lo, float hi) {
    u64 r; asm("mov.b64 %0, {%1, %2};" : "=l"(r) : "f"(lo), "f"(hi)); return r;
}
__device__ __forceinline__ void unpack2(u64 v, float& lo, float& hi) {
    asm("mov.b64 {%0, %1}, %2;" : "=f"(lo), "=f"(hi) : "l"(v));
}
__device__ __forceinline__ u64 fma2(u64 a, u64 b, u64 c) {
    u64 d; asm("fma.rn.f32x2 %0, %1, %2, %3;" : "=l"(d) : "l"(a), "l"(b), "l"(c)); return d;
}
__device__ __forceinline__ u64 mul2(u64 a, u64 b) {
    u64 d; asm("mul.rn.f32x2 %0, %1, %2;" : "=l"(d) : "l"(a), "l"(b)); return d;
}
// weights: streaming, evict-first (protect x in L1)
__device__ __forceinline__ int4 ldg_cs(const int* p) {
    int4 v;
    asm("ld.global.cs.v4.u32 {%0,%1,%2,%3}, [%4];"
        : "=r"(v.x), "=r"(v.y), "=r"(v.z), "=r"(v.w) : "l"(p));
    return v;
}
// x: keep resident in L1
__device__ __forceinline__ ulonglong2 ldg_x(const float* p) {
    ulonglong2 v;
    asm("ld.global.nc.L1::evict_last.v2.u64 {%0,%1}, [%2];"
        : "=l"(v.x), "=l"(v.y) : "l"(p));
    return v;
}

// ---- prekernel: Sx[b][g] = sum of x over group g (warp per (b,g)) ----
__global__ void prep_kernel(const float* __restrict__ x) {
    const int gt   = blockIdx.x * blockDim.x + threadIdx.x;
    const int w    = gt >> 5;            // 0..255 = b*32 + g
    const int lane = gt & 31;
    const int base = (w >> 5) * IN_F + (w & 31) * GS + lane * 4;
    float4 v = __ldg((const float4*)(x + base));
    float s = (v.x + v.y) + (v.z + v.w);
    #pragma unroll
    for (int off = 16; off > 0; off >>= 1)
        s += __shfl_xor_sync(0xffffffffu, s, off);
    if (lane == 0) g_sx[w] = s;
}

// ---- main kernel ----
__global__ void __launch_bounds__(TPB, 8)
w4a32_main(const float* __restrict__ x, const int* __restrict__ qw,
           const float* __restrict__ sc, const float* __restrict__ zr,
           float* __restrict__ out)
{
    __shared__ float bounce[WPB][OPW * BATCH];

    const int tid  = threadIdx.x;
    const int warp = tid >> 5;
    const int lane = tid & 31;
    const int n0   = (blockIdx.x * WPB + warp) * OPW;
    const int klo  = lane * 4;

    const int* qbase = qw + (long)n0 * IN_F + klo;

    // prefetch group 0 weights + scales into registers
    int4 q[OPW];
    #pragma unroll
    for (int o = 0; o < OPW; ++o) q[o] = ldg_cs(qbase + o * IN_F);
    float4 sv = __ldg((const float4*)(sc + n0));

    u64 acc[OPW][BATCH];
    #pragma unroll
    for (int o = 0; o < OPW; ++o)
        #pragma unroll
        for (int b = 0; b < BATCH; ++b) acc[o][b] = 0ull;

    #pragma unroll 1
    for (int g = 0; g < NG; ++g) {
        // convert current group: qs[o] = float(q) * s  (pairs along k)
        u64 qs[OPW][2];
        {
            float sa[OPW] = {sv.x, sv.y, sv.z, sv.w};
            #pragma unroll
            for (int o = 0; o < OPW; ++o) {
                u64 s2 = pack2(sa[o], sa[o]);
                qs[o][0] = mul2(pack2((float)q[o].x, (float)q[o].y), s2);
                qs[o][1] = mul2(pack2((float)q[o].z, (float)q[o].w), s2);
            }
        }

        // prefetch next group's weights + scales (regs now free)
        const int gn = (g + 1) & (NG - 1);
        #pragma unroll
        for (int o = 0; o < OPW; ++o) q[o] = ldg_cs(qbase + gn * GS + o * IN_F);
        sv = __ldg((const float4*)(sc + gn * OUT_F + n0));

        // inner: x pairs from L1-resident x, 8 batches x 4 outputs
        const float* xg = x + g * GS + klo;
        #pragma unroll
        for (int b = 0; b < BATCH; ++b) {
            ulonglong2 xp = ldg_x(xg + b * IN_F);
            #pragma unroll
            for (int o = 0; o < OPW; ++o) {
                acc[o][b] = fma2(xp.x, qs[o][0], acc[o][b]);
                acc[o][b] = fma2(xp.y, qs[o][1], acc[o][b]);
            }
        }
    }

    // ---- pair-halves add, butterfly across 32 lanes ----
    float r[OPW][BATCH];
    #pragma unroll
    for (int o = 0; o < OPW; ++o)
        #pragma unroll
        for (int b = 0; b < BATCH; ++b) {
            float lo, hi; unpack2(acc[o][b], lo, hi);
            r[o][b] = lo + hi;
        }
    #pragma unroll
    for (int off = 16; off > 0; off >>= 1)
        #pragma unroll
        for (int o = 0; o < OPW; ++o)
            #pragma unroll
            for (int b = 0; b < BATCH; ++b)
                r[o][b] += __shfl_xor_sync(0xffffffffu, r[o][b], off);

    if (lane == 0) {
        #pragma unroll
        for (int o = 0; o < OPW; ++o)
            #pragma unroll
            for (int b = 0; b < BATCH; ++b)
                bounce[warp][o * BATCH + b] = r[o][b];
    }
    __syncwarp();

    // 32 results per warp, one per lane; fold in zero/offset term here
    const int o = lane >> 3, b = lane & 7;
    const int n = n0 + o;
    float offt = 0.f;
    #pragma unroll
    for (int g2 = 0; g2 < NG; ++g2) {
        float s = __ldg(sc + g2 * OUT_F + n);
        float z = __ldg(zr + g2 * OUT_F + n);
        offt = fmaf(z - 8.f * s, g_sx[b * NG + g2], offt);
    }
    out[b * OUT_F + n] = bounce[warp][lane] + offt;
}

extern "C" void kernel_launch(void* const* d_in, const int* in_sizes, int n_in,
                              void* d_out, int out_size) {
    const float* x  = (const float*)d_in[0];
    const int*   qw = (const int*)d_in[1];
    const float* sc = (const float*)d_in[2];
    const float* zr = (const float*)d_in[3];
    float* out = (float*)d_out;

    prep_kernel<<<32, 256>>>(x);
    w4a32_main<<<OUT_F / (WPB * OPW), TPB>>>(x, qw, sc, zr, out);  // 1536 x 64
}

// round 5
// speedup vs baseline: 1.2743x; 1.2743x over previous
#include <cuda_runtime.h>
#include <cstdint>

#define BATCH 8
#define IN_F 4096
#define OUT_F 12288
#define GS 128
#define NG 32
#define OPW 4          // outputs per warp
#define WPB 2          // warps per block
#define TPB (WPB * 32)

typedef unsigned long long u64;

__device__ float g_sx[BATCH * NG];      // per-batch per-group sums of x

__device__ __forceinline__ u64 pack2(float lo, float hi) {
    u64 r; asm("mov.b64 %0, {%1, %2};" : "=l"(r) : "f"(lo), "f"(hi)); return r;
}
__device__ __forceinline__ void unpack2(u64 v, float& lo, float& hi) {
    asm("mov.b64 {%0, %1}, %2;" : "=f"(lo), "=f"(hi) : "l"(v));
}
__device__ __forceinline__ u64 fma2(u64 a, u64 b, u64 c) {
    u64 d; asm("fma.rn.f32x2 %0, %1, %2, %3;" : "=l"(d) : "l"(a), "l"(b), "l"(c)); return d;
}
__device__ __forceinline__ u64 mul2(u64 a, u64 b) {
    u64 d; asm("mul.rn.f32x2 %0, %1, %2;" : "=l"(d) : "l"(a), "l"(b)); return d;
}
// weights: streaming, evict-first (protect x in L1)
__device__ __forceinline__ int4 ldg_cs(const int* p) {
    int4 v;
    asm("ld.global.cs.v4.u32 {%0,%1,%2,%3}, [%4];"
        : "=r"(v.x), "=r"(v.y), "=r"(v.z), "=r"(v.w) : "l"(p));
    return v;
}
// x: keep resident in L1
__device__ __forceinline__ float4 ldg_x4(const float* p) {
    float4 v;
    asm("ld.global.nc.L1::evict_last.v4.f32 {%0,%1,%2,%3}, [%4];"
        : "=f"(v.x), "=f"(v.y), "=f"(v.z), "=f"(v.w) : "l"(p));
    return v;
}

// ---- prekernel: Sx[b][g] = sum of x over group g (warp per (b,g)) ----
__global__ void prep_kernel(const float* __restrict__ x) {
    const int gt   = blockIdx.x * blockDim.x + threadIdx.x;
    const int w    = gt >> 5;            // 0..255 = b*32 + g
    const int lane = gt & 31;
    const int base = (w >> 5) * IN_F + (w & 31) * GS + lane * 4;
    float4 v = __ldg((const float4*)(x + base));
    float s = (v.x + v.y) + (v.z + v.w);
    #pragma unroll
    for (int off = 16; off > 0; off >>= 1)
        s += __shfl_xor_sync(0xffffffffu, s, off);
    if (lane == 0) g_sx[w] = s;
}

// ---- main kernel ----
__global__ void __launch_bounds__(TPB, 8)
w4a32_main(const float* __restrict__ x, const int* __restrict__ qw,
           const float* __restrict__ sc, const float* __restrict__ zr,
           float* __restrict__ out)
{
    __shared__ float bounce[WPB][OPW * BATCH];

    const int tid  = threadIdx.x;
    const int warp = tid >> 5;
    const int lane = tid & 31;
    const int n0   = (blockIdx.x * WPB + warp) * OPW;
    const int klo  = lane * 4;

    const int* qbase = qw + (long)n0 * IN_F + klo;

    // prefetch groups 0 and 1 (depth-2 register pipeline)
    int4 qbuf[2][OPW];
    float4 svbuf[2];
    #pragma unroll
    for (int s = 0; s < 2; ++s) {
        #pragma unroll
        for (int o = 0; o < OPW; ++o)
            qbuf[s][o] = ldg_cs(qbase + s * GS + o * IN_F);
        svbuf[s] = __ldg((const float4*)(sc + s * OUT_F + n0));
    }

    // accumulators paired over OUTPUTS: accA = (n0+0, n0+1), accB = (n0+2, n0+3)
    u64 accA[BATCH], accB[BATCH];
    #pragma unroll
    for (int b = 0; b < BATCH; ++b) { accA[b] = 0ull; accB[b] = 0ull; }

    #pragma unroll 2
    for (int g = 0; g < NG; ++g) {
        const int cur = g & 1;

        // convert current group: qsA[k] = (s0*q0k, s1*q1k), qsB[k] = (s2*q2k, s3*q3k)
        u64 qsA[4], qsB[4];
        {
            const float4 sv = svbuf[cur];
            const u64 sp01 = pack2(sv.x, sv.y);
            const u64 sp23 = pack2(sv.z, sv.w);
            const int4 q0 = qbuf[cur][0], q1 = qbuf[cur][1];
            const int4 q2 = qbuf[cur][2], q3 = qbuf[cur][3];
            qsA[0] = mul2(pack2((float)q0.x, (float)q1.x), sp01);
            qsA[1] = mul2(pack2((float)q0.y, (float)q1.y), sp01);
            qsA[2] = mul2(pack2((float)q0.z, (float)q1.z), sp01);
            qsA[3] = mul2(pack2((float)q0.w, (float)q1.w), sp01);
            qsB[0] = mul2(pack2((float)q2.x, (float)q3.x), sp23);
            qsB[1] = mul2(pack2((float)q2.y, (float)q3.y), sp23);
            qsB[2] = mul2(pack2((float)q2.z, (float)q3.z), sp23);
            qsB[3] = mul2(pack2((float)q2.w, (float)q3.w), sp23);
        }

        // issue loads for group g+2 into the buffer just consumed
        {
            const int gn = (g + 2) & (NG - 1);
            #pragma unroll
            for (int o = 0; o < OPW; ++o)
                qbuf[cur][o] = ldg_cs(qbase + gn * GS + o * IN_F);
            svbuf[cur] = __ldg((const float4*)(sc + gn * OUT_F + n0));
        }

        // math: 8 batches x 4 k x 2 output-pairs
        const float* xg = x + g * GS + klo;
        #pragma unroll
        for (int b = 0; b < BATCH; ++b) {
            float4 xv = ldg_x4(xg + b * IN_F);
            u64 x0 = pack2(xv.x, xv.x);
            u64 x1 = pack2(xv.y, xv.y);
            u64 x2 = pack2(xv.z, xv.z);
            u64 x3 = pack2(xv.w, xv.w);
            accA[b] = fma2(x0, qsA[0], accA[b]);
            accB[b] = fma2(x0, qsB[0], accB[b]);
            accA[b] = fma2(x1, qsA[1], accA[b]);
            accB[b] = fma2(x1, qsB[1], accB[b]);
            accA[b] = fma2(x2, qsA[2], accA[b]);
            accB[b] = fma2(x2, qsB[2], accB[b]);
            accA[b] = fma2(x3, qsA[3], accA[b]);
            accB[b] = fma2(x3, qsB[3], accB[b]);
        }
    }

    // ---- split pairs back into per-output scalars, butterfly across lanes ----
    float r[OPW][BATCH];
    #pragma unroll
    for (int b = 0; b < BATCH; ++b) {
        unpack2(accA[b], r[0][b], r[1][b]);
        unpack2(accB[b], r[2][b], r[3][b]);
    }
    #pragma unroll
    for (int off = 16; off > 0; off >>= 1)
        #pragma unroll
        for (int o = 0; o < OPW; ++o)
            #pragma unroll
            for (int b = 0; b < BATCH; ++b)
                r[o][b] += __shfl_xor_sync(0xffffffffu, r[o][b], off);

    if (lane == 0) {
        #pragma unroll
        for (int o = 0; o < OPW; ++o)
            #pragma unroll
            for (int b = 0; b < BATCH; ++b)
                bounce[warp][o * BATCH + b] = r[o][b];
    }
    __syncwarp();

    // 32 results per warp, one per lane; fold in zero/offset term here
    const int o = lane >> 3, b = lane & 7;
    const int n = n0 + o;
    float offt = 0.f;
    #pragma unroll
    for (int g2 = 0; g2 < NG; ++g2) {
        float s = __ldg(sc + g2 * OUT_F + n);
        float z = __ldg(zr + g2 * OUT_F + n);
        offt = fmaf(z - 8.f * s, g_sx[b * NG + g2], offt);
    }
    out[b * OUT_F + n] = bounce[warp][lane] + offt;
}

extern "C" void kernel_launch(void* const* d_in, const int* in_sizes, int n_in,
                              void* d_out, int out_size) {
    const float* x  = (const float*)d_in[0];
    const int*   qw = (const int*)d_in[1];
    const float* sc = (const float*)d_in[2];
    const float* zr = (const float*)d_in[3];
    float* out = (float*)d_out;

    prep_kernel<<<32, 256>>>(x);
    w4a32_main<<<OUT_F / (WPB * OPW), TPB>>>(x, qw, sc, zr, out);  // 1536 x 64
}

// round 6
// speedup vs baseline: 1.3763x; 1.0800x over previous
#include <cuda_runtime.h>
#include <cstdint>

#define BATCH 8
#define IN_F 4096
#define OUT_F 12288
#define GS 128
#define NG 32
#define OPW 4          // outputs per warp
#define TPB 32         // one warp per CTA

typedef unsigned long long u64;

__device__ float g_sx[BATCH * NG];      // per-batch per-group sums of x

__device__ __forceinline__ u64 pack2(float lo, float hi) {
    u64 r; asm("mov.b64 %0, {%1, %2};" : "=l"(r) : "f"(lo), "f"(hi)); return r;
}
__device__ __forceinline__ void unpack2(u64 v, float& lo, float& hi) {
    asm("mov.b64 {%0, %1}, %2;" : "=f"(lo), "=f"(hi) : "l"(v));
}
__device__ __forceinline__ u64 fma2(u64 a, u64 b, u64 c) {
    u64 d; asm("fma.rn.f32x2 %0, %1, %2, %3;" : "=l"(d) : "l"(a), "l"(b), "l"(c)); return d;
}
__device__ __forceinline__ u64 mul2(u64 a, u64 b) {
    u64 d; asm("mul.rn.f32x2 %0, %1, %2;" : "=l"(d) : "l"(a), "l"(b)); return d;
}
// weights: streaming, evict-first (protect x in L1)
__device__ __forceinline__ int4 ldg_cs(const int* p) {
    int4 v;
    asm("ld.global.cs.v4.u32 {%0,%1,%2,%3}, [%4];"
        : "=r"(v.x), "=r"(v.y), "=r"(v.z), "=r"(v.w) : "l"(p));
    return v;
}
// x: pairs along k, keep resident in L1
__device__ __forceinline__ ulonglong2 ldg_x2(const float* p) {
    ulonglong2 v;
    asm("ld.global.nc.L1::evict_last.v2.u64 {%0,%1}, [%2];"
        : "=l"(v.x), "=l"(v.y) : "l"(p));
    return v;
}

// ---- prekernel: Sx[b][g] = sum of x over group g (warp per (b,g)) ----
__global__ void prep_kernel(const float* __restrict__ x) {
    const int gt   = blockIdx.x * blockDim.x + threadIdx.x;
    const int w    = gt >> 5;            // 0..255 = b*32 + g
    const int lane = gt & 31;
    const int base = (w >> 5) * IN_F + (w & 31) * GS + lane * 4;
    float4 v = __ldg((const float4*)(x + base));
    float s = (v.x + v.y) + (v.z + v.w);
    #pragma unroll
    for (int off = 16; off > 0; off >>= 1)
        s += __shfl_xor_sync(0xffffffffu, s, off);
    if (lane == 0) g_sx[w] = s;
}

// ---- main kernel: one warp per 4 outputs ----
__global__ void __launch_bounds__(TPB, 12)
w4a32_main(const float* __restrict__ x, const int* __restrict__ qw,
           const float* __restrict__ sc, const float* __restrict__ zr,
           float* __restrict__ out)
{
    __shared__ float bounce[OPW * BATCH];

    const int lane = threadIdx.x;
    const int n0   = blockIdx.x * OPW;
    const int klo  = lane * 4;

    const int* qbase = qw + (long)n0 * IN_F + klo;

    // weights: register pipeline depth 2
    int4 qbuf[2][OPW];
    float4 svbuf[2];
    #pragma unroll
    for (int s = 0; s < 2; ++s) {
        #pragma unroll
        for (int o = 0; o < OPW; ++o)
            qbuf[s][o] = ldg_cs(qbase + s * GS + o * IN_F);
        svbuf[s] = __ldg((const float4*)(sc + s * OUT_F + n0));
    }

    // x: register pipeline depth 1 (pairs along k)
    ulonglong2 xcur[BATCH];
    #pragma unroll
    for (int b = 0; b < BATCH; ++b)
        xcur[b] = ldg_x2(x + b * IN_F + klo);

    u64 acc[OPW][BATCH];
    #pragma unroll
    for (int o = 0; o < OPW; ++o)
        #pragma unroll
        for (int b = 0; b < BATCH; ++b) acc[o][b] = 0ull;

    #pragma unroll 2
    for (int g = 0; g < NG; ++g) {
        const int cur = g & 1;

        // convert current group: qs[o] = (s*q0,s*q1),(s*q2,s*q3)
        u64 qs[OPW][2];
        {
            const float4 sv = svbuf[cur];
            const float sa[OPW] = {sv.x, sv.y, sv.z, sv.w};
            #pragma unroll
            for (int o = 0; o < OPW; ++o) {
                const int4 q = qbuf[cur][o];
                u64 s2 = pack2(sa[o], sa[o]);
                qs[o][0] = mul2(pack2((float)q.x, (float)q.y), s2);
                qs[o][1] = mul2(pack2((float)q.z, (float)q.w), s2);
            }
        }

        // prefetch weights + scales for g+2 into the buffer just consumed
        {
            const int gn2 = (g + 2) & (NG - 1);
            #pragma unroll
            for (int o = 0; o < OPW; ++o)
                qbuf[cur][o] = ldg_cs(qbase + gn2 * GS + o * IN_F);
            svbuf[cur] = __ldg((const float4*)(sc + gn2 * OUT_F + n0));
        }

        // math for group g; per-batch, reload x for g+1 right after consuming
        const float* xg1 = x + ((g + 1) & (NG - 1)) * GS + klo;
        #pragma unroll
        for (int b = 0; b < BATCH; ++b) {
            const ulonglong2 xv = xcur[b];
            xcur[b] = ldg_x2(xg1 + b * IN_F);   // half-iteration-ahead prefetch
            #pragma unroll
            for (int o = 0; o < OPW; ++o) {
                acc[o][b] = fma2(xv.x, qs[o][0], acc[o][b]);
                acc[o][b] = fma2(xv.y, qs[o][1], acc[o][b]);
            }
        }
    }

    // ---- pair-halves add, butterfly across 32 lanes ----
    float r[OPW][BATCH];
    #pragma unroll
    for (int o = 0; o < OPW; ++o)
        #pragma unroll
        for (int b = 0; b < BATCH; ++b) {
            float lo, hi; unpack2(acc[o][b], lo, hi);
            r[o][b] = lo + hi;
        }
    #pragma unroll
    for (int off = 16; off > 0; off >>= 1)
        #pragma unroll
        for (int o = 0; o < OPW; ++o)
            #pragma unroll
            for (int b = 0; b < BATCH; ++b)
                r[o][b] += __shfl_xor_sync(0xffffffffu, r[o][b], off);

    if (lane == 0) {
        #pragma unroll
        for (int o = 0; o < OPW; ++o)
            #pragma unroll
            for (int b = 0; b < BATCH; ++b)
                bounce[o * BATCH + b] = r[o][b];
    }
    __syncwarp();

    // 32 results, one per lane; fold in zero/offset term here
    const int o = lane >> 3, b = lane & 7;
    const int n = n0 + o;
    float offt = 0.f;
    #pragma unroll
    for (int g2 = 0; g2 < NG; ++g2) {
        float s = __ldg(sc + g2 * OUT_F + n);
        float z = __ldg(zr + g2 * OUT_F + n);
        offt = fmaf(z - 8.f * s, g_sx[b * NG + g2], offt);
    }
    out[b * OUT_F + n] = bounce[lane] + offt;
}

extern "C" void kernel_launch(void* const* d_in, const int* in_sizes, int n_in,
                              void* d_out, int out_size) {
    const float* x  = (const float*)d_in[0];
    const int*   qw = (const int*)d_in[1];
    const float* sc = (const float*)d_in[2];
    const float* zr = (const float*)d_in[3];
    float* out = (float*)d_out;

    prep_kernel<<<32, 256>>>(x);
    w4a32_main<<<OUT_F / OPW, TPB>>>(x, qw, sc, zr, out);   // 3072 x 32
}